// round 12
// baseline (speedup 1.0000x reference)
#include <cuda_runtime.h>

#define NN   50000
#define NSEG 150000          // 3 relations x NN segments, v = r*NN + node
#define NT   256
#define EMAX 4500000
#define SCAN_BS 1024

// ---------------- scratch (static device globals; no allocs) ----------------
__device__ int   g_is64;
__device__ int   g_dout[NSEG];           // out-degree per (r,node)
__device__ int   g_din [NSEG];           // in-degree per (r,node)
__device__ int2  g_edges [EMAX];         // compact (src seg, dst seg), input order
__device__ int2  g_sorted[EMAX];         // SRC-grouped edges
__device__ int   g_cur [NSEG];           // fill cursors (from dout scan)
__device__ int   g_part[256];            // scan block partials
__device__ float g_h1 [NSEG * 16];       // rsqrt(dout)-scaled layer-1 features
__device__ float g_m  [NSEG * 16];       // aggregation buffers
__device__ float g_s  [NSEG];            // scalar layer-2 messages
__device__ float g_o2 [NSEG];            // scalar layer-2 accumulators

// ---------------- dtype detection ----------------
__global__ void k_detect(const unsigned* __restrict__ p, int n) {
    __shared__ int found;
    if (threadIdx.x == 0) found = 0;
    __syncthreads();
    int f = 0;
    for (int i = threadIdx.x; i < n; i += blockDim.x)
        if (p[2 * i + 1] != 0u) f = 1;
    if (f) atomicOr(&found, 1);
    __syncthreads();
    if (threadIdx.x == 0) g_is64 = found ? 0 : 1;
}

__device__ __forceinline__ int ldidx(const void* __restrict__ p, int i) {
    return g_is64 ? (int)__ldg((const long long*)p + i)
                  : __ldg((const int*)p + i);
}

__device__ __forceinline__ float rs_of(int cnt) {
    return rsqrtf((float)(cnt > 0 ? cnt : 1));
}

// ---------------- zero counters ----------------
__global__ void k_zero() {
    int i = blockIdx.x * blockDim.x + threadIdx.x;
    if (i < NSEG) { g_dout[i] = 0; g_din[i] = 0; }
}

// ------- degrees + compact int2 edge emit (single pass over raw idx) --------
__global__ void k_degc(const void* __restrict__ src, const void* __restrict__ dst,
                       int E, int r, int eoff) {
    int e = blockIdx.x * blockDim.x + threadIdx.x;
    if (e >= E) return;
    int s = r * NN + ldidx(src, e);
    int d = r * NN + ldidx(dst, e);
    atomicAdd(&g_dout[s], 1);
    atomicAdd(&g_din [d], 1);
    g_edges[eoff + e] = make_int2(s, d);
}

// ---------------- exclusive scan over g_dout (for src grouping) -------------
__global__ void k_scan1() {
    __shared__ int ws[32];
    int b = blockIdx.x, t = threadIdx.x;
    int v = b * SCAN_BS + t;
    int val = (v < NSEG) ? g_dout[v] : 0;
    #pragma unroll
    for (int o = 16; o; o >>= 1) val += __shfl_down_sync(0xffffffffu, val, o);
    if ((t & 31) == 0) ws[t >> 5] = val;
    __syncthreads();
    if (t < 32) {
        int x = ws[t];
        #pragma unroll
        for (int o = 16; o; o >>= 1) x += __shfl_down_sync(0xffffffffu, x, o);
        if (t == 0) g_part[b] = x;
    }
}

__global__ void k_scan2(int nblk) {
    __shared__ int sh[256];
    int t = threadIdx.x;
    sh[t] = (t < nblk) ? g_part[t] : 0;
    __syncthreads();
    for (int o = 1; o < 256; o <<= 1) {
        int y = (t >= o) ? sh[t - o] : 0;
        __syncthreads();
        sh[t] += y;
        __syncthreads();
    }
    if (t < nblk) g_part[t] = (t == 0) ? 0 : sh[t - 1];
}

__global__ void k_scan3() {
    __shared__ int ws[32];
    int b = blockIdx.x, t = threadIdx.x;
    int v = b * SCAN_BS + t;
    int lane = t & 31, wid = t >> 5;
    int val = (v < NSEG) ? g_dout[v] : 0;
    int x = val;
    #pragma unroll
    for (int o = 1; o < 32; o <<= 1) {
        int y = __shfl_up_sync(0xffffffffu, x, o);
        if (lane >= o) x += y;
    }
    if (lane == 31) ws[wid] = x;
    __syncthreads();
    if (wid == 0) {
        int w = ws[lane];
        #pragma unroll
        for (int o = 1; o < 32; o <<= 1) {
            int y = __shfl_up_sync(0xffffffffu, w, o);
            if (lane >= o) w += y;
        }
        ws[lane] = w;
    }
    __syncthreads();
    int base = g_part[b] + (wid > 0 ? ws[wid - 1] : 0);
    if (v < NSEG) g_cur[v] = base + x - val;   // exclusive prefix
}

// ---------------- group edges by SRC via cursor scatter ----------------
__global__ void k_fill(int Etot) {
    int e = blockIdx.x * blockDim.x + threadIdx.x;
    if (e >= Etot) return;
    int2 ed = __ldg((const int2*)&g_edges[e]);
    int pos = atomicAdd(&g_cur[ed.x], 1);
    g_sorted[pos] = ed;
}

// ---------------- layer 1: per-node transform (and zero g_m) ----------------
__global__ void k_layer1_node(const float* __restrict__ x, const float* __restrict__ W1) {
    __shared__ float sW[3 * 32 * 16];
    for (int i = threadIdx.x; i < 1536; i += blockDim.x) sW[i] = W1[i];
    __syncthreads();
    int n = blockIdx.x * blockDim.x + threadIdx.x;
    if (n >= NN) return;
    float xv[32];
    #pragma unroll
    for (int j = 0; j < 8; j++) {
        float4 v = __ldg((const float4*)(x + (size_t)n * 32) + j);
        xv[4*j] = v.x; xv[4*j+1] = v.y; xv[4*j+2] = v.z; xv[4*j+3] = v.w;
    }
    #pragma unroll
    for (int r = 0; r < 3; r++) {
        float a = rs_of(g_dout[r * NN + n]);
        float y[16];
        #pragma unroll
        for (int f = 0; f < 16; f++) y[f] = 0.f;
        #pragma unroll
        for (int j = 0; j < 32; j++) {
            float xj = xv[j];
            #pragma unroll
            for (int f = 0; f < 16; f++)
                y[f] += xj * sW[r * 512 + j * 16 + f];
        }
        float* hp = &g_h1[(size_t)(r * NN + n) * 16];
        float* mp = &g_m [(size_t)(r * NN + n) * 16];
        #pragma unroll
        for (int f = 0; f < 16; f += 4) {
            *(float4*)(hp + f) = make_float4(a*y[f], a*y[f+1], a*y[f+2], a*y[f+3]);
            *(float4*)(mp + f) = make_float4(0.f, 0.f, 0.f, 0.f);
        }
    }
}

// ---- layer 1 scatter on SRC-GROUPED edges: 4 lanes/edge, R3 shape ----------
// Same-src runs make the h1 load an L1 broadcast/hit; REDs unchanged.
__global__ void k_scatter16(int Etot) {
    long long t = (long long)blockIdx.x * blockDim.x + threadIdx.x;
    if (t >= (long long)Etot * 4) return;
    int e = (int)(t >> 2), c = (int)(t & 3);
    int2 ed = *(const int2*)&g_sorted[e];         // 4 lanes same addr: broadcast
    const float4 v = __ldg((const float4*)&g_h1[(size_t)ed.x * 16] + c);
    float* mp = &g_m[(size_t)ed.y * 16 + c * 4];
    asm volatile("red.global.add.v4.f32 [%0], {%1, %2, %3, %4};"
                 :: "l"(mp), "f"(v.x), "f"(v.y), "f"(v.z), "f"(v.w) : "memory");
}

// ---------------- combine + relu + layer-2 node transform (zero g_o2) -------
__global__ void k_combine(const float* __restrict__ b1, const float* __restrict__ W2) {
    __shared__ float sW2[48], sb1[48];
    if (threadIdx.x < 48) {
        sW2[threadIdx.x] = W2[threadIdx.x];
        sb1[threadIdx.x] = b1[threadIdx.x];
    }
    __syncthreads();
    int n = blockIdx.x * blockDim.x + threadIdx.x;
    if (n >= NN) return;
    float acc[16];
    #pragma unroll
    for (int f = 0; f < 16; f++) acc[f] = 0.f;
    #pragma unroll
    for (int r = 0; r < 3; r++) {
        float ain = rs_of(g_din[r * NN + n]);
        const float* mp = &g_m[(size_t)(r * NN + n) * 16];
        #pragma unroll
        for (int f = 0; f < 16; f += 4) {
            float4 v = *(const float4*)(mp + f);
            acc[f]   += v.x * ain + sb1[r*16 + f];
            acc[f+1] += v.y * ain + sb1[r*16 + f + 1];
            acc[f+2] += v.z * ain + sb1[r*16 + f + 2];
            acc[f+3] += v.w * ain + sb1[r*16 + f + 3];
        }
    }
    #pragma unroll
    for (int f = 0; f < 16; f++) acc[f] = fmaxf(acc[f], 0.f);
    #pragma unroll
    for (int r = 0; r < 3; r++) {
        float aout = rs_of(g_dout[r * NN + n]);
        float dot = 0.f;
        #pragma unroll
        for (int f = 0; f < 16; f++) dot += acc[f] * sW2[r*16 + f];
        g_s [r * NN + n] = aout * dot;
        g_o2[r * NN + n] = 0.f;
    }
}

// ---- layer 2 scatter on SRC-GROUPED edges: g_s load broadcasts too ---------
__global__ void k_scatter1(int Etot) {
    int e = blockIdx.x * blockDim.x + threadIdx.x;
    if (e >= Etot) return;
    int2 ed = __ldg((const int2*)&g_sorted[e]);
    float v = __ldg(&g_s[ed.x]);
    atomicAdd(&g_o2[ed.y], v);
}

// ---------------- final ----------------
__global__ void k_final(float* __restrict__ out, const float* __restrict__ b2) {
    int n = blockIdx.x * blockDim.x + threadIdx.x;
    if (n >= NN) return;
    float o = __ldg(b2) + __ldg(b2 + 1) + __ldg(b2 + 2);
    #pragma unroll
    for (int r = 0; r < 3; r++)
        o += g_o2[r * NN + n] * rs_of(g_din[r * NN + n]);
    out[n] = o;
}

// ---------------- host ----------------
extern "C" void kernel_launch(void* const* d_in, const int* in_sizes, int n_in,
                              void* d_out, int out_size) {
    const float* x  = (const float*)d_in[0];
    const void*  src[3] = { d_in[1], d_in[3], d_in[5] };
    const void*  dst[3] = { d_in[2], d_in[4], d_in[6] };
    int          E[3]   = { in_sizes[1], in_sizes[3], in_sizes[5] };
    const float* W1 = (const float*)d_in[7];
    const float* b1 = (const float*)d_in[8];
    const float* W2 = (const float*)d_in[9];
    const float* b2 = (const float*)d_in[10];
    float*       out = (float*)d_out;

    int Etot = E[0] + E[1] + E[2];
    if (Etot > EMAX) Etot = EMAX;

    int nprobe = E[0] < 2048 ? E[0] : 2048;
    k_detect<<<1, NT>>>((const unsigned*)d_in[1], nprobe);

    k_zero<<<(NSEG + NT - 1) / NT, NT>>>();
    int eoff = 0;
    for (int r = 0; r < 3; r++) {
        k_degc<<<(E[r] + NT - 1) / NT, NT>>>(src[r], dst[r], E[r], r, eoff);
        eoff += E[r];
    }

    int nblk = (NSEG + SCAN_BS - 1) / SCAN_BS;   // 147
    k_scan1<<<nblk, SCAN_BS>>>();
    k_scan2<<<1, 256>>>(nblk);
    k_scan3<<<nblk, SCAN_BS>>>();
    k_fill<<<(Etot + NT - 1) / NT, NT>>>(Etot);

    k_layer1_node<<<(NN + NT - 1) / NT, NT>>>(x, W1);
    {
        long long work = (long long)Etot * 4;
        int blocks = (int)((work + NT - 1) / NT);
        k_scatter16<<<blocks, NT>>>(Etot);
    }

    k_combine<<<(NN + NT - 1) / NT, NT>>>(b1, W2);
    k_scatter1<<<(Etot + NT - 1) / NT, NT>>>(Etot);

    k_final<<<(NN + NT - 1) / NT, NT>>>(out, b2);
}

// round 13
// speedup vs baseline: 1.3129x; 1.3129x over previous
#include <cuda_runtime.h>

#define NN   50000
#define NSEG 150000
#define NT   256
#define EMAX 4500000

// ---------------- scratch (static device globals; no allocs) ----------------
__device__ int   g_is64;                 // 1 if edge indices are int64, 0 if int32
__device__ int   g_cnt[6 * NN];          // [2r]=deg_out(src), [2r+1]=deg_in(dst)
__device__ int2  g_edges[EMAX + 4];      // compacted (src + r*NN, dst + r*NN), padded
__device__ float g_h1 [NSEG * 16];       // per-relation scaled layer-1 features
__device__ float g_m  [NSEG * 16];       // per-relation aggregation buffers
__device__ float g_s  [NSEG];            // per-relation scalar layer-2 messages
__device__ float g_o2 [NSEG];            // per-relation scalar aggregation

// ---------------- dtype detection ----------------
__global__ void k_detect(const unsigned* __restrict__ p, int n) {
    __shared__ int found;
    if (threadIdx.x == 0) found = 0;
    __syncthreads();
    int f = 0;
    for (int i = threadIdx.x; i < n; i += blockDim.x)
        if (p[2 * i + 1] != 0u) f = 1;
    if (f) atomicOr(&found, 1);
    __syncthreads();
    if (threadIdx.x == 0) g_is64 = found ? 0 : 1;
}

__device__ __forceinline__ int ldidx(const void* __restrict__ p, int i) {
    return g_is64 ? (int)__ldg((const long long*)p + i)
                  : __ldg((const int*)p + i);
}

__device__ __forceinline__ float rs_of(int cnt) {
    return rsqrtf((float)(cnt > 0 ? cnt : 1));
}

// ---------------- zero counters + pad edges ----------------
__global__ void k_zero_cnt() {
    int i = blockIdx.x * blockDim.x + threadIdx.x;
    if (i < 6 * NN) g_cnt[i] = 0;
    if (i < 4) g_edges[EMAX + i] = make_int2(0, 0);
}

// ---------------- degrees + index compaction (single pass) ----------------
__global__ void k_degc(const void* __restrict__ src, const void* __restrict__ dst,
                       int E, int r, int eoff) {
    int e = blockIdx.x * blockDim.x + threadIdx.x;
    if (e >= E) return;
    int s = ldidx(src, e);
    int d = ldidx(dst, e);
    atomicAdd(&g_cnt[(2 * r)     * NN + s], 1);
    atomicAdd(&g_cnt[(2 * r + 1) * NN + d], 1);
    g_edges[eoff + e] = make_int2(r * NN + s, r * NN + d);
}

// ---------------- layer 1: per-node transform (and zero g_m) ----------------
__global__ void k_layer1_node(const float* __restrict__ x, const float* __restrict__ W1) {
    __shared__ float sW[3 * 32 * 16];
    for (int i = threadIdx.x; i < 1536; i += blockDim.x) sW[i] = W1[i];
    __syncthreads();
    int n = blockIdx.x * blockDim.x + threadIdx.x;
    if (n >= NN) return;
    float xv[32];
    #pragma unroll
    for (int j = 0; j < 8; j++) {
        float4 v = __ldg((const float4*)(x + (size_t)n * 32) + j);
        xv[4*j] = v.x; xv[4*j+1] = v.y; xv[4*j+2] = v.z; xv[4*j+3] = v.w;
    }
    #pragma unroll
    for (int r = 0; r < 3; r++) {
        float a = rs_of(g_cnt[(2 * r) * NN + n]);
        float y[16];
        #pragma unroll
        for (int f = 0; f < 16; f++) y[f] = 0.f;
        #pragma unroll
        for (int j = 0; j < 32; j++) {
            float xj = xv[j];
            #pragma unroll
            for (int f = 0; f < 16; f++)
                y[f] += xj * sW[r * 512 + j * 16 + f];
        }
        float* hp = &g_h1[(size_t)(r * NN + n) * 16];
        float* mp = &g_m [(size_t)(r * NN + n) * 16];
        #pragma unroll
        for (int f = 0; f < 16; f += 4) {
            *(float4*)(hp + f) = make_float4(a*y[f], a*y[f+1], a*y[f+2], a*y[f+3]);
            *(float4*)(mp + f) = make_float4(0.f, 0.f, 0.f, 0.f);
        }
    }
}

// ---- layer 1 scatter: 4-lane chunk split, 4 EDGES PER THREAD (MLP=6) -------
// Thread (g, c): edges 4g..4g+3, chunk c. Two int4 idx loads (broadcast in
// the 4-lane group), then 4 independent LDG.128 + 4 fire-and-forget RED.128.
__global__ void k_scatter16(int Etot) {
    long long t = (long long)blockIdx.x * blockDim.x + threadIdx.x;
    int c = (int)(t & 3);
    long long g = t >> 2;
    int e0 = (int)(g << 2);
    if (e0 >= Etot) return;
    const int4* ep = (const int4*)g_edges;
    int4 q0 = __ldg(ep + 2 * g);        // edges e0, e0+1
    int4 q1 = __ldg(ep + 2 * g + 1);    // edges e0+2, e0+3 (padded region safe)
    int rem = Etot - e0;                // >= 1

    const float4* h0 = (const float4*)&g_h1[(size_t)q0.x * 16] + c;
    const float4* h1p = (const float4*)&g_h1[(size_t)q0.z * 16] + c;
    const float4* h2 = (const float4*)&g_h1[(size_t)q1.x * 16] + c;
    const float4* h3 = (const float4*)&g_h1[(size_t)q1.z * 16] + c;

    float4 v0 = __ldg(h0);
    float4 v1 = (rem > 1) ? __ldg(h1p) : make_float4(0.f,0.f,0.f,0.f);
    float4 v2 = (rem > 2) ? __ldg(h2)  : make_float4(0.f,0.f,0.f,0.f);
    float4 v3 = (rem > 3) ? __ldg(h3)  : make_float4(0.f,0.f,0.f,0.f);

    {
        float* mp = &g_m[(size_t)q0.y * 16 + c * 4];
        asm volatile("red.global.add.v4.f32 [%0], {%1, %2, %3, %4};"
                     :: "l"(mp), "f"(v0.x), "f"(v0.y), "f"(v0.z), "f"(v0.w) : "memory");
    }
    if (rem > 1) {
        float* mp = &g_m[(size_t)q0.w * 16 + c * 4];
        asm volatile("red.global.add.v4.f32 [%0], {%1, %2, %3, %4};"
                     :: "l"(mp), "f"(v1.x), "f"(v1.y), "f"(v1.z), "f"(v1.w) : "memory");
    }
    if (rem > 2) {
        float* mp = &g_m[(size_t)q1.y * 16 + c * 4];
        asm volatile("red.global.add.v4.f32 [%0], {%1, %2, %3, %4};"
                     :: "l"(mp), "f"(v2.x), "f"(v2.y), "f"(v2.z), "f"(v2.w) : "memory");
    }
    if (rem > 3) {
        float* mp = &g_m[(size_t)q1.w * 16 + c * 4];
        asm volatile("red.global.add.v4.f32 [%0], {%1, %2, %3, %4};"
                     :: "l"(mp), "f"(v3.x), "f"(v3.y), "f"(v3.z), "f"(v3.w) : "memory");
    }
}

// ---------------- combine + relu + layer-2 node transform (zero g_o2) -------
__global__ void k_combine(const float* __restrict__ b1, const float* __restrict__ W2) {
    __shared__ float sW2[48], sb1[48];
    if (threadIdx.x < 48) {
        sW2[threadIdx.x] = W2[threadIdx.x];
        sb1[threadIdx.x] = b1[threadIdx.x];
    }
    __syncthreads();
    int n = blockIdx.x * blockDim.x + threadIdx.x;
    if (n >= NN) return;
    float acc[16];
    #pragma unroll
    for (int f = 0; f < 16; f++) acc[f] = 0.f;
    #pragma unroll
    for (int r = 0; r < 3; r++) {
        float ain = rs_of(g_cnt[(2 * r + 1) * NN + n]);
        const float* mp = &g_m[(size_t)(r * NN + n) * 16];
        #pragma unroll
        for (int f = 0; f < 16; f += 4) {
            float4 v = *(const float4*)(mp + f);
            acc[f]   += v.x * ain + sb1[r*16 + f];
            acc[f+1] += v.y * ain + sb1[r*16 + f + 1];
            acc[f+2] += v.z * ain + sb1[r*16 + f + 2];
            acc[f+3] += v.w * ain + sb1[r*16 + f + 3];
        }
    }
    #pragma unroll
    for (int f = 0; f < 16; f++) acc[f] = fmaxf(acc[f], 0.f);
    #pragma unroll
    for (int r = 0; r < 3; r++) {
        float aout = rs_of(g_cnt[(2 * r) * NN + n]);
        float dot = 0.f;
        #pragma unroll
        for (int f = 0; f < 16; f++) dot += acc[f] * sW2[r*16 + f];
        g_s [r * NN + n] = aout * dot;
        g_o2[r * NN + n] = 0.f;
    }
}

// ---- layer 2: scalar edge scatter, 4 EDGES PER THREAD ----------------------
__global__ void k_scatter1(int Etot) {
    int t = blockIdx.x * blockDim.x + threadIdx.x;
    int e0 = t << 2;
    if (e0 >= Etot) return;
    const int4* ep = (const int4*)g_edges;
    int4 q0 = __ldg(ep + 2 * t);
    int4 q1 = __ldg(ep + 2 * t + 1);
    int rem = Etot - e0;
    float v0 = __ldg(&g_s[q0.x]);
    float v1 = (rem > 1) ? __ldg(&g_s[q0.z]) : 0.f;
    float v2 = (rem > 2) ? __ldg(&g_s[q1.x]) : 0.f;
    float v3 = (rem > 3) ? __ldg(&g_s[q1.z]) : 0.f;
    atomicAdd(&g_o2[q0.y], v0);
    if (rem > 1) atomicAdd(&g_o2[q0.w], v1);
    if (rem > 2) atomicAdd(&g_o2[q1.y], v2);
    if (rem > 3) atomicAdd(&g_o2[q1.w], v3);
}

// ---------------- final ----------------
__global__ void k_final(float* __restrict__ out, const float* __restrict__ b2) {
    int n = blockIdx.x * blockDim.x + threadIdx.x;
    if (n >= NN) return;
    float o = __ldg(b2) + __ldg(b2 + 1) + __ldg(b2 + 2);
    #pragma unroll
    for (int r = 0; r < 3; r++)
        o += g_o2[r * NN + n] * rs_of(g_cnt[(2 * r + 1) * NN + n]);
    out[n] = o;
}

// ---------------- host ----------------
extern "C" void kernel_launch(void* const* d_in, const int* in_sizes, int n_in,
                              void* d_out, int out_size) {
    const float* x  = (const float*)d_in[0];
    const void*  src[3] = { d_in[1], d_in[3], d_in[5] };
    const void*  dst[3] = { d_in[2], d_in[4], d_in[6] };
    int          E[3]   = { in_sizes[1], in_sizes[3], in_sizes[5] };
    const float* W1 = (const float*)d_in[7];
    const float* b1 = (const float*)d_in[8];
    const float* W2 = (const float*)d_in[9];
    const float* b2 = (const float*)d_in[10];
    float*       out = (float*)d_out;

    int Etot = E[0] + E[1] + E[2];
    if (Etot > EMAX) Etot = EMAX;

    int nprobe = E[0] < 2048 ? E[0] : 2048;
    k_detect<<<1, NT>>>((const unsigned*)d_in[1], nprobe);

    k_zero_cnt<<<(6 * NN + NT - 1) / NT, NT>>>();
    int eoff = 0;
    for (int r = 0; r < 3; r++) {
        k_degc<<<(E[r] + NT - 1) / NT, NT>>>(src[r], dst[r], E[r], r, eoff);
        eoff += E[r];
    }

    k_layer1_node<<<(NN + NT - 1) / NT, NT>>>(x, W1);
    {
        long long groups = ((long long)Etot + 3) / 4;
        long long work = groups * 4;                  // 4 lanes per group
        int blocks = (int)((work + NT - 1) / NT);
        k_scatter16<<<blocks, NT>>>(Etot);
    }

    k_combine<<<(NN + NT - 1) / NT, NT>>>(b1, W2);
    {
        int thr = (Etot + 3) / 4;
        k_scatter1<<<(thr + NT - 1) / NT, NT>>>(Etot);
    }

    k_final<<<(NN + NT - 1) / NT, NT>>>(out, b2);
}